// round 15
// baseline (speedup 1.0000x reference)
#include <cuda_runtime.h>
#include <cuda_fp16.h>
#include <math.h>
#include <stdint.h>

#define B_   2
#define T_   2048
#define C_   1024
#define H_   16
#define D_   64
#define M_   4096          // B_*T_
#define N1_  3072          // 3*C_
#define EPS_ 1e-6f

// ---------------- scratch (device globals; no allocation allowed) ----------------
__device__ float g_xsq[M_];
__device__ float g_osq[M_];
__device__ float g_wsq1[N1_];
__device__ float g_wsq2[C_];
__device__ __half g_xh[(size_t)M_ * C_];
__device__ __half g_ah[(size_t)M_ * C_];
__device__ __half g_w1h[(size_t)N1_ * C_];  // [N,K] transposed
__device__ __half g_w2h[(size_t)C_ * C_];
__device__ __half g_qbh[(size_t)B_ * H_ * T_ * D_];  // [B,H,T,D] (scaled)
__device__ __half g_kbh[(size_t)B_ * H_ * T_ * D_];  // [B,H,T,D]
__device__ __half g_vth[(size_t)B_ * H_ * D_ * T_];  // [B,H,D,T]

__device__ __forceinline__ float fast_exp2(float x) {
    float r;
    asm("ex2.approx.ftz.f32 %0, %1;" : "=f"(r) : "f"(x));
    return r;
}

__device__ __forceinline__ uint32_t smem_u32(const void* p) {
    return (uint32_t)__cvta_generic_to_shared(p);
}

__device__ __forceinline__ uint32_t pack_f16(float lo, float hi) {
    uint32_t r;
    asm("cvt.rn.f16x2.f32 %0, %1, %2;" : "=r"(r) : "f"(hi), "f"(lo));
    return r;
}

// ======================= small helper kernels =======================

__global__ void prep_x_kernel(const float* __restrict__ X, float* __restrict__ xsq,
                              __half* __restrict__ Xh)
{
    int m = blockIdx.x;
    int tid = threadIdx.x;
    size_t i = (size_t)m * C_ + tid * 4;
    float4 v = *(const float4*)(X + i);
    *(__half2*)(Xh + i)     = __floats2half2_rn(v.x, v.y);
    *(__half2*)(Xh + i + 2) = __floats2half2_rn(v.z, v.w);

    float s = v.x * v.x + v.y * v.y + v.z * v.z + v.w * v.w;
#pragma unroll
    for (int o = 16; o; o >>= 1) s += __shfl_xor_sync(0xffffffffu, s, o);
    __shared__ float red[8];
    if ((tid & 31) == 0) red[tid >> 5] = s;
    __syncthreads();
    if (tid == 0) {
        float t = 0.f;
#pragma unroll
        for (int j = 0; j < 8; j++) t += red[j];
        xsq[m] = t;
    }
}

__global__ void wconv_kernel(const float* __restrict__ W,
                             __half* __restrict__ WhT,
                             float* __restrict__ wsq,
                             int K, int N)
{
    __shared__ float tile[32][33];
    int bx = blockIdx.x, by = blockIdx.y;
    int tx = threadIdx.x & 31, ty = threadIdx.x >> 5;
#pragma unroll
    for (int i = ty; i < 32; i += 8)
        tile[i][tx] = W[(size_t)(by * 32 + i) * N + bx * 32 + tx];
    __syncthreads();
#pragma unroll
    for (int i = ty; i < 32; i += 8) {
        int n = bx * 32 + i, k = by * 32 + tx;
        float v = tile[tx][i];
        WhT[(size_t)n * K + k] = __float2half_rn(v);
        float s = v * v;
#pragma unroll
        for (int o = 16; o; o >>= 1) s += __shfl_xor_sync(0xffffffffu, s, o);
        if (tx == 0) atomicAdd(wsq + n, s);
    }
}

// ======================= mma.sync helpers =======================

#define LDSM4(r0, r1, r2, r3, addr) \
    asm volatile("ldmatrix.sync.aligned.m8n8.x4.shared.b16 {%0,%1,%2,%3}, [%4];" \
                 : "=r"(r0), "=r"(r1), "=r"(r2), "=r"(r3) : "r"(addr))

#define MMA16816(d, a, b) \
    asm volatile("mma.sync.aligned.m16n8k16.row.col.f32.f16.f16.f32 " \
                 "{%0,%1,%2,%3}, {%4,%5,%6,%7}, {%8,%9}, {%0,%1,%2,%3};" \
                 : "+f"((d)[0]), "+f"((d)[1]), "+f"((d)[2]), "+f"((d)[3]) \
                 : "r"((a)[0]), "r"((a)[1]), "r"((a)[2]), "r"((a)[3]), \
                   "r"((b)[0]), "r"((b)[1]))

__device__ __forceinline__ void cp16(uint32_t dst, const void* src) {
    asm volatile("cp.async.cg.shared.global [%0], [%1], 16;" :: "r"(dst), "l"(src));
}

// ======================= GEMM core (pure fp16, warp 64x32, 8 warps, 3-stage) =======================
#define ROWB   144
#define TILEB  (128 * ROWB)
#define OFF_A  0
#define OFF_B  TILEB
#define STAGEB (2 * TILEB)
#define MMA_SMEM (3 * STAGEB)

__device__ __forceinline__ void load_stage(
    uint32_t st, const __half* Ag, const __half* Bg,
    int k0, int K, int tid)
{
#pragma unroll
    for (int it = 0; it < 4; it++) {
        int idx = it * 256 + tid;
        int row = idx >> 3;
        int ch = (idx & 7) * 16;
        uint32_t dst = (uint32_t)row * ROWB + ch;
        size_t srcel = (size_t)row * K + k0;
        cp16(st + OFF_A + dst, (const char*)(Ag + srcel) + ch);
        cp16(st + OFF_B + dst, (const char*)(Bg + srcel) + ch);
    }
}

__device__ __forceinline__ void ld_frags(uint32_t aB, uint32_t bB, int ks,
                                         uint32_t a[4][4], uint32_t b[4][2])
{
#pragma unroll
    for (int mt = 0; mt < 4; mt++)
        LDSM4(a[mt][0], a[mt][1], a[mt][2], a[mt][3],
              aB + mt * (16 * ROWB) + ks * 32);
#pragma unroll
    for (int nt2 = 0; nt2 < 2; nt2++) {
        uint32_t r0, r1, r2, r3;
        LDSM4(r0, r1, r2, r3, bB + nt2 * (16 * ROWB) + ks * 32);
        b[nt2 * 2 + 0][0] = r0; b[nt2 * 2 + 0][1] = r1;
        b[nt2 * 2 + 1][0] = r2; b[nt2 * 2 + 1][1] = r3;
    }
}

__device__ __forceinline__ void gemm_chunk(
    uint32_t st, uint32_t aSel, uint32_t bSel, int warpM, int warpN,
    float acc[4][4][4])
{
    const uint32_t aB = st + OFF_A + (uint32_t)warpM * 64 * ROWB + aSel;
    const uint32_t bB = st + OFF_B + (uint32_t)warpN * 32 * ROWB + bSel;
    uint32_t a[2][4][4], b[2][4][2];
    ld_frags(aB, bB, 0, a[0], b[0]);
#pragma unroll
    for (int ks = 0; ks < 4; ks++) {
        const int cur = ks & 1;
        if (ks < 3) ld_frags(aB, bB, ks + 1, a[cur ^ 1], b[cur ^ 1]);
#pragma unroll
        for (int mt = 0; mt < 4; mt++)
#pragma unroll
            for (int nt = 0; nt < 4; nt++)
                MMA16816(acc[mt][nt], a[cur][mt], b[cur][nt]);
    }
}

#define GEMM_MAIN(Agh, Bgh, K)                                                 \
    float acc[4][4][4];                                                        \
    _Pragma("unroll")                                                          \
    for (int i = 0; i < 4; i++)                                                \
        _Pragma("unroll")                                                      \
        for (int j = 0; j < 4; j++)                                            \
            _Pragma("unroll")                                                  \
            for (int e = 0; e < 4; e++) acc[i][j][e] = 0.f;                    \
    load_stage(sb, Agh, Bgh, 0, K, tid);                                       \
    asm volatile("cp.async.commit_group;" ::: "memory");                       \
    load_stage(sb + STAGEB, Agh, Bgh, 64, K, tid);                             \
    asm volatile("cp.async.commit_group;" ::: "memory");                       \
    const int NC = (K) >> 6;                                                   \
    int slot = 0;                                                              \
    for (int c = 0; c < NC; c++) {                                             \
        if (c + 1 < NC) {                                                      \
            asm volatile("cp.async.wait_group 1;" ::: "memory");               \
        } else {                                                               \
            asm volatile("cp.async.wait_group 0;" ::: "memory");               \
        }                                                                      \
        __syncthreads();                                                       \
        const uint32_t stb = sb + (uint32_t)slot * STAGEB;                     \
        if (++slot == 3) slot = 0;                                             \
        if (c + 2 < NC) {                                                      \
            int ns = slot + 1; if (ns == 3) ns = 0;                            \
            load_stage(sb + (uint32_t)ns * STAGEB, Agh, Bgh, (c + 2) << 6, K,  \
                       tid);                                                   \
            asm volatile("cp.async.commit_group;" ::: "memory");               \
        }                                                                      \
        gemm_chunk(stb, aSel, bSel, warpM, warpN, acc);                        \
    }

// ======================= GEMM2: yat -> fp32 out =======================
__global__ void __launch_bounds__(256, 2) yat_mma_gemm_kernel(
    const __half* __restrict__ Ah, const __half* __restrict__ BhT,
    const float* __restrict__ asq, const float* __restrict__ bsq,
    const float* __restrict__ bias, float* __restrict__ Cout,
    int M, int N, int K, float scale)
{
    extern __shared__ char smem[];
    const uint32_t sb = smem_u32(smem);

    const int tid = threadIdx.x;
    const int wid = tid >> 5, lane = tid & 31;
    const int warpM = wid >> 2;
    const int warpN = wid & 3;
    const int rowBase = blockIdx.y * 128;
    const int colBase = blockIdx.x * 128;

    const __half* Agh = Ah + (size_t)rowBase * K;
    const __half* Bgh = BhT + (size_t)colBase * K;

    const uint32_t aSel = (uint32_t)(lane & 15) * ROWB + (uint32_t)(lane >> 4) * 16;
    const uint32_t bSel = (uint32_t)(((lane >> 4) & 1) * 8 + (lane & 7)) * ROWB +
                          (uint32_t)((lane >> 3) & 1) * 16;

    GEMM_MAIN(Agh, Bgh, K)

    const int lr = lane >> 2, lc = (lane & 3) * 2;
    const int mW = rowBase + warpM * 64;
    const int nW = colBase + warpN * 32;
#pragma unroll
    for (int mt = 0; mt < 4; mt++) {
        const int r0g = mW + mt * 16 + lr;
        const int r1g = r0g + 8;
        const float av0 = asq[r0g];
        const float av1 = asq[r1g];
#pragma unroll
        for (int nt = 0; nt < 4; nt++) {
            const int cg = nW + nt * 8 + lc;
            const float bq0 = bsq[cg], bq1 = bsq[cg + 1];
            const float bi0 = bias[cg], bi1 = bias[cg + 1];
            float d00 = acc[mt][nt][0], d01 = acc[mt][nt][1];
            float d10 = acc[mt][nt][2], d11 = acc[mt][nt][3];
            float2 o0, o1;
            o0.x = __fdividef(d00 * d00, av0 + bq0 - 2.f * d00 + EPS_) * scale + bi0;
            o0.y = __fdividef(d01 * d01, av0 + bq1 - 2.f * d01 + EPS_) * scale + bi1;
            o1.x = __fdividef(d10 * d10, av1 + bq0 - 2.f * d10 + EPS_) * scale + bi0;
            o1.y = __fdividef(d11 * d11, av1 + bq1 - 2.f * d11 + EPS_) * scale + bi1;
            *(float2*)(Cout + (size_t)r0g * N + cg) = o0;
            *(float2*)(Cout + (size_t)r1g * N + cg) = o1;
        }
    }
}

// ======================= GEMM1: yat + RoPE + fp16 fused epilogue =======================
__global__ void __launch_bounds__(256, 2) yat_rope_gemm_kernel(
    const __half* __restrict__ Ah, const __half* __restrict__ BhT,
    const float* __restrict__ asq, const float* __restrict__ bsq,
    const float* __restrict__ bias,
    __half* __restrict__ Qh, __half* __restrict__ Kh,
    __half* __restrict__ VTh,
    float scale)
{
    extern __shared__ char smem[];
    const uint32_t sb = smem_u32(smem);
    const int K = C_;

    const int tid = threadIdx.x;
    const int wid = tid >> 5, lane = tid & 31;
    const int warpM = wid >> 2;
    const int warpN = wid & 3;
    const int rowBase = blockIdx.y * 128;
    const int colBase = blockIdx.x * 128;

    const __half* Agh = Ah + (size_t)rowBase * K;
    const __half* Bgh = BhT + (size_t)colBase * K;

    const uint32_t aSel = (uint32_t)(lane & 15) * ROWB + (uint32_t)(lane >> 4) * 16;
    const uint32_t bSel = (uint32_t)(((lane >> 4) & 1) * 8 + (lane & 7)) * ROWB +
                          (uint32_t)((lane >> 3) & 1) * 16;

    GEMM_MAIN(Agh, Bgh, K)

    const int lr = lane >> 2, lc = (lane & 3) * 2;
    const int mW = rowBase + warpM * 64;
    const int nW = colBase + warpN * 32;
    const int seg = colBase >> 10;                 // 0=Q, 1=K, 2=V
    const float QSC = 0.125f * 1.4426950408889634f;

    float fr[4];
#pragma unroll
    for (int nt = 0; nt < 4; nt++) {
        int cg = nW + nt * 8 + lc;
        int i = (cg & 63) >> 1;
        fr[nt] = powf(10000.0f, -(float)i / 32.0f);
    }

#pragma unroll
    for (int mt = 0; mt < 4; mt++) {
        const int r0g = mW + mt * 16 + lr;
        const int r1g = r0g + 8;
        const float av0 = asq[r0g];
        const float av1 = asq[r1g];
        const int b0 = r0g >> 11, t0 = r0g & 2047;
        const int b1 = r1g >> 11, t1 = r1g & 2047;
#pragma unroll
        for (int nt = 0; nt < 4; nt++) {
            const int cg = nW + nt * 8 + lc;
            const float bq0 = bsq[cg], bq1 = bsq[cg + 1];
            const float bi0 = bias[cg], bi1 = bias[cg + 1];
            float d00 = acc[mt][nt][0], d01 = acc[mt][nt][1];
            float d10 = acc[mt][nt][2], d11 = acc[mt][nt][3];
            float y00 = __fdividef(d00 * d00, av0 + bq0 - 2.f * d00 + EPS_) * scale + bi0;
            float y01 = __fdividef(d01 * d01, av0 + bq1 - 2.f * d01 + EPS_) * scale + bi1;
            float y10 = __fdividef(d10 * d10, av1 + bq0 - 2.f * d10 + EPS_) * scale + bi0;
            float y11 = __fdividef(d11 * d11, av1 + bq1 - 2.f * d11 + EPS_) * scale + bi1;

            const int colh = cg & 1023;
            const int h = colh >> 6;
            const int d = colh & 63;

            if (seg < 2) {
                float s0, c0, s1, c1;
                sincosf((float)t0 * fr[nt], &s0, &c0);
                sincosf((float)t1 * fr[nt], &s1, &c1);
                float sc = (seg == 0) ? QSC : 1.0f;
                float a0 = (y00 * c0 - y01 * s0) * sc;
                float a1 = (y01 * c0 + y00 * s0) * sc;
                float e0 = (y10 * c1 - y11 * s1) * sc;
                float e1 = (y11 * c1 + y10 * s1) * sc;
                __half* Dst = (seg == 0) ? Qh : Kh;
                size_t o0 = ((size_t)(b0 * H_ + h) * T_ + t0) * D_ + d;
                size_t o1 = ((size_t)(b1 * H_ + h) * T_ + t1) * D_ + d;
                *(__half2*)(Dst + o0) = __floats2half2_rn(a0, a1);
                *(__half2*)(Dst + o1) = __floats2half2_rn(e0, e1);
            } else {
                size_t ov0 = ((size_t)(b0 * H_ + h) * D_ + d) * T_ + t0;
                size_t ov1 = ((size_t)(b1 * H_ + h) * D_ + d) * T_ + t1;
                VTh[ov0]      = __float2half_rn(y00);
                VTh[ov0 + T_] = __float2half_rn(y01);
                VTh[ov1]      = __float2half_rn(y10);
                VTh[ov1 + T_] = __float2half_rn(y11);
            }
        }
    }
}

// ======================= tensor-core causal flash attention (pure fp16, 3-stage) =======================
#define AROWB 144
#define QTILE (128 * AROWB)
#define KVTILE (64 * AROWB)
#define SQH_OFF 0
#define STG_OFF QTILE
#define STGSZ  (2 * KVTILE)
#define ST_KH 0
#define ST_VH (1 * KVTILE)
#define ATTN_SMEM (QTILE + 3 * STGSZ)

__device__ __forceinline__ void attn_load_stage(
    uint32_t st, const __half* kh, const __half* vth,
    size_t bhT, size_t bhD, int k0, int tid)
{
#pragma unroll
    for (int it = 0; it < 2; it++) {
        int idx = it * 256 + tid;
        int row = idx >> 3;
        int ch = (idx & 7) * 16;
        uint32_t dst = (uint32_t)row * AROWB + ch;
        cp16(st + ST_KH + dst, (const char*)(kh + (bhT + k0 + row) * D_) + ch);
        cp16(st + ST_VH + dst, (const char*)(vth + (bhD + row) * T_ + k0) + ch);
    }
}

__global__ void __launch_bounds__(256, 2) attn_mma_kernel(
    const __half* __restrict__ qh, const __half* __restrict__ kh,
    const __half* __restrict__ vth,
    __half* __restrict__ Oh, float* __restrict__ osq)
{
    extern __shared__ char smem[];
    const uint32_t sb = smem_u32(smem);

    const int bh = blockIdx.y;
    const int qx = 15 - (int)blockIdx.x;
    const int q0 = qx * 128;
    const size_t bhT = (size_t)bh * T_;
    const size_t bhD = (size_t)bh * D_;

    const int tid = threadIdx.x;
    const int wid = tid >> 5, lane = tid & 31;
    const int lr = lane >> 2, c2 = (lane & 3) * 2;

    const uint32_t aSel = (uint32_t)(lane & 15) * AROWB + (uint32_t)(lane >> 4) * 16;
    const uint32_t bSel = (uint32_t)(((lane >> 4) & 1) * 8 + (lane & 7)) * AROWB +
                          (uint32_t)((lane >> 3) & 1) * 16;

    const int ntiles = 2 * qx + 2;

#pragma unroll
    for (int it = 0; it < 4; it++) {
        int idx = it * 256 + tid;
        int row = idx >> 3;
        int ch = (idx & 7) * 16;
        uint32_t dst = (uint32_t)row * AROWB + ch;
        cp16(sb + SQH_OFF + dst, (const char*)(qh + (bhT + q0 + row) * D_) + ch);
    }
    attn_load_stage(sb + STG_OFF, kh, vth, bhT, bhD, 0, tid);
    asm volatile("cp.async.commit_group;" ::: "memory");
    attn_load_stage(sb + STG_OFF + STGSZ, kh, vth, bhT, bhD, 64, tid);
    asm volatile("cp.async.commit_group;" ::: "memory");

    asm volatile("cp.async.wait_group 1;" ::: "memory");
    __syncthreads();
    uint32_t qhf[4][4];
    {
        const uint32_t aQ = sb + SQH_OFF + (uint32_t)wid * 16 * AROWB + aSel;
#pragma unroll
        for (int ks = 0; ks < 4; ks++)
            LDSM4(qhf[ks][0], qhf[ks][1], qhf[ks][2], qhf[ks][3], aQ + ks * 32);
    }

    float O[8][4];
#pragma unroll
    for (int j = 0; j < 8; j++)
#pragma unroll
        for (int e = 0; e < 4; e++) O[j][e] = 0.f;
    float mrow[2] = {-1e30f, -1e30f};
    float lrow[2] = {0.f, 0.f};

    const int rowg0 = q0 + wid * 16 + lr;
    int slot = 0;

    for (int kt = 0; kt < ntiles; kt++) {
        if (kt + 1 < ntiles) {
            asm volatile("cp.async.wait_group 1;" ::: "memory");
        } else {
            asm volatile("cp.async.wait_group 0;" ::: "memory");
        }
        __syncthreads();
        const uint32_t st = sb + STG_OFF + (uint32_t)slot * STGSZ;
        if (++slot == 3) slot = 0;
        if (kt + 2 < ntiles) {
            int ns = slot + 1; if (ns == 3) ns = 0;
            attn_load_stage(sb + STG_OFF + (uint32_t)ns * STGSZ,
                            kh, vth, bhT, bhD, (kt + 2) * 64, tid);
            asm volatile("cp.async.commit_group;" ::: "memory");
        }

        float S[8][4];
#pragma unroll
        for (int j = 0; j < 8; j++)
#pragma unroll
            for (int e = 0; e < 4; e++) S[j][e] = 0.f;

#pragma unroll
        for (int ks = 0; ks < 4; ks++) {
#pragma unroll
            for (int np = 0; np < 4; np++) {
                uint32_t r0, r1, r2, r3;
                LDSM4(r0, r1, r2, r3, st + ST_KH + np * (16 * AROWB) + bSel + ks * 32);
                uint32_t bh0[2] = {r0, r1}, bh1[2] = {r2, r3};
                MMA16816(S[np * 2 + 0], qhf[ks], bh0);
                MMA16816(S[np * 2 + 1], qhf[ks], bh1);
            }
        }

        const int k0 = kt * 64;
        if (kt >= 2 * qx) {
#pragma unroll
            for (int j = 0; j < 8; j++) {
                int col = k0 + j * 8 + c2;
                if (col > rowg0)     S[j][0] = -1e30f;
                if (col + 1 > rowg0) S[j][1] = -1e30f;
                if (col > rowg0 + 8)     S[j][2] = -1e30f;
                if (col + 1 > rowg0 + 8) S[j][3] = -1e30f;
            }
        }

#pragma unroll
        for (int i = 0; i < 2; i++) {
            float mx = -1e30f;
#pragma unroll
            for (int j = 0; j < 8; j++)
                mx = fmaxf(mx, fmaxf(S[j][2 * i], S[j][2 * i + 1]));
            mx = fmaxf(mx, __shfl_xor_sync(0xffffffffu, mx, 1));
            mx = fmaxf(mx, __shfl_xor_sync(0xffffffffu, mx, 2));
            float mn = fmaxf(mrow[i], mx);
            float cf = fast_exp2(mrow[i] - mn);
            mrow[i] = mn;
            float rs = 0.f;
#pragma unroll
            for (int j = 0; j < 8; j++) {
                float p0 = fast_exp2(S[j][2 * i] - mn);
                float p1 = fast_exp2(S[j][2 * i + 1] - mn);
                S[j][2 * i] = p0; S[j][2 * i + 1] = p1;
                rs += p0 + p1;
            }
            rs += __shfl_xor_sync(0xffffffffu, rs, 1);
            rs += __shfl_xor_sync(0xffffffffu, rs, 2);
            lrow[i] = lrow[i] * cf + rs;
#pragma unroll
            for (int j = 0; j < 8; j++) { O[j][2 * i] *= cf; O[j][2 * i + 1] *= cf; }
        }

        uint32_t PH[4][4];
#pragma unroll
        for (int t = 0; t < 4; t++) {
#pragma unroll
            for (int h2 = 0; h2 < 2; h2++) {
                int j = 2 * t + h2;
                PH[t][h2 * 2 + 0] = pack_f16(S[j][0], S[j][1]);
                PH[t][h2 * 2 + 1] = pack_f16(S[j][2], S[j][3]);
            }
        }

#pragma unroll
        for (int t = 0; t < 4; t++) {
#pragma unroll
            for (int dn = 0; dn < 4; dn++) {
                uint32_t r0, r1, r2, r3;
                LDSM4(r0, r1, r2, r3, st + ST_VH + dn * (16 * AROWB) + bSel + t * 32);
                uint32_t vh0[2] = {r0, r1}, vh1[2] = {r2, r3};
                MMA16816(O[dn * 2 + 0], PH[t], vh0);
                MMA16816(O[dn * 2 + 1], PH[t], vh1);
            }
        }
    }

    const int b = bh >> 4, h = bh & 15;
    const float inv0 = 1.f / lrow[0], inv1 = 1.f / lrow[1];
    const size_t m0 = (size_t)(b * T_ + rowg0);
    const size_t m1 = m0 + 8;
    __half* oh0 = Oh + m0 * C_ + h * 64;
    __half* oh1 = Oh + m1 * C_ + h * 64;
    float sq0 = 0.f, sq1 = 0.f;
#pragma unroll
    for (int j = 0; j < 8; j++) {
        float y0 = O[j][0] * inv0, y1 = O[j][1] * inv0;
        float y2 = O[j][2] * inv1, y3 = O[j][3] * inv1;
        sq0 += y0 * y0 + y1 * y1;
        sq1 += y2 * y2 + y3 * y3;
        *(__half2*)(oh0 + j * 8 + c2) = __floats2half2_rn(y0, y1);
        *(__half2*)(oh1 + j * 8 + c2) = __floats2half2_rn(y2, y3);
    }
    sq0 += __shfl_xor_sync(0xffffffffu, sq0, 1);
    sq0 += __shfl_xor_sync(0xffffffffu, sq0, 2);
    sq1 += __shfl_xor_sync(0xffffffffu, sq1, 1);
    sq1 += __shfl_xor_sync(0xffffffffu, sq1, 2);
    if ((lane & 3) == 0) {
        atomicAdd(osq + m0, sq0);
        atomicAdd(osq + m1, sq1);
    }
}

// ---------------- launcher (fork/join side stream for weight prep) ----------------
extern "C" void kernel_launch(void* const* d_in, const int* in_sizes, int n_in,
                              void* d_out, int out_size)
{
    (void)in_sizes; (void)n_in; (void)out_size;
    const float* x      = (const float*)d_in[0];
    const float* w_attn = (const float*)d_in[2];
    const float* b_attn = (const float*)d_in[3];
    const float* w_proj = (const float*)d_in[4];
    const float* b_proj = (const float*)d_in[5];
    float* out = (float*)d_out;

    float *xsq, *osq, *wsq1, *wsq2;
    __half *xh, *ah, *w1h, *w2h;
    __half *qbh, *kbh, *vth;
    cudaGetSymbolAddress((void**)&xsq,  g_xsq);
    cudaGetSymbolAddress((void**)&osq,  g_osq);
    cudaGetSymbolAddress((void**)&wsq1, g_wsq1);
    cudaGetSymbolAddress((void**)&wsq2, g_wsq2);
    cudaGetSymbolAddress((void**)&xh,   g_xh);
    cudaGetSymbolAddress((void**)&ah,   g_ah);
    cudaGetSymbolAddress((void**)&w1h,  g_w1h);
    cudaGetSymbolAddress((void**)&w2h,  g_w2h);
    cudaGetSymbolAddress((void**)&qbh,  g_qbh);
    cudaGetSymbolAddress((void**)&kbh,  g_kbh);
    cudaGetSymbolAddress((void**)&vth,  g_vth);

    const float scale1 = (float)(sqrt(3072.0) / log1p(3072.0));
    const float scale2 = (float)(sqrt(1024.0) / log1p(1024.0));

    cudaFuncSetAttribute(yat_mma_gemm_kernel,
                         cudaFuncAttributeMaxDynamicSharedMemorySize, MMA_SMEM);
    cudaFuncSetAttribute(yat_rope_gemm_kernel,
                         cudaFuncAttributeMaxDynamicSharedMemorySize, MMA_SMEM);
    cudaFuncSetAttribute(attn_mma_kernel,
                         cudaFuncAttributeMaxDynamicSharedMemorySize, ATTN_SMEM);

    // fork/join side stream (host-side objects only; created per call, leaked —
    // kernel_launch runs only for correctness + capture, not in the timed replay)
    cudaStream_t s2;
    cudaEvent_t evFork, evA, evB;
    cudaStreamCreateWithFlags(&s2, cudaStreamNonBlocking);
    cudaEventCreateWithFlags(&evFork, cudaEventDisableTiming);
    cudaEventCreateWithFlags(&evA, cudaEventDisableTiming);
    cudaEventCreateWithFlags(&evB, cudaEventDisableTiming);

    cudaEventRecord(evFork, 0);
    cudaStreamWaitEvent(s2, evFork, 0);

    // side stream: weight prep (wconv1 gates GEMM1, wconv2 gates GEMM2)
    cudaMemsetAsync(wsq1, 0, N1_ * sizeof(float), s2);
    wconv_kernel<<<dim3(N1_ / 32, C_ / 32), 256, 0, s2>>>(w_attn, w1h, wsq1, C_, N1_);
    cudaEventRecord(evA, s2);
    cudaMemsetAsync(wsq2, 0, C_ * sizeof(float), s2);
    wconv_kernel<<<dim3(C_ / 32, C_ / 32), 256, 0, s2>>>(w_proj, w2h, wsq2, C_, C_);
    cudaEventRecord(evB, s2);

    // main stream: x prep overlaps wconv1
    cudaMemsetAsync(osq, 0, M_ * sizeof(float));
    prep_x_kernel<<<M_, 256>>>(x, xsq, xh);

    cudaStreamWaitEvent(0, evA, 0);
    yat_rope_gemm_kernel<<<dim3(N1_ / 128, M_ / 128), 256, MMA_SMEM>>>(
        xh, w1h, xsq, wsq1, b_attn, qbh, kbh, vth, scale1);

    attn_mma_kernel<<<dim3(T_ / 128, B_ * H_), 256, ATTN_SMEM>>>(
        qbh, kbh, vth, ah, osq);

    cudaStreamWaitEvent(0, evB, 0);
    yat_mma_gemm_kernel<<<dim3(C_ / 128, M_ / 128), 256, MMA_SMEM>>>(
        ah, w2h, osq, wsq2, b_proj, out, M_, C_, C_, scale2);
}

// round 16
// speedup vs baseline: 1.4910x; 1.4910x over previous
#include <cuda_runtime.h>
#include <cuda_fp16.h>
#include <math.h>
#include <stdint.h>

#define B_   2
#define T_   2048
#define C_   1024
#define H_   16
#define D_   64
#define M_   4096          // B_*T_
#define N1_  3072          // 3*C_
#define EPS_ 1e-6f

// ---------------- scratch (device globals; no allocation allowed) ----------------
__device__ float g_xsq[M_];
__device__ float g_osq[M_];
__device__ float g_wsq1[N1_];
__device__ float g_wsq2[C_];
__device__ __half g_xh[(size_t)M_ * C_];
__device__ __half g_ah[(size_t)M_ * C_];
__device__ __half g_w1h[(size_t)N1_ * C_];  // [N,K] transposed
__device__ __half g_w2h[(size_t)C_ * C_];
__device__ __half g_qbh[(size_t)B_ * H_ * T_ * D_];  // [B,H,T,D] (scaled)
__device__ __half g_kbh[(size_t)B_ * H_ * T_ * D_];  // [B,H,T,D]
__device__ __half g_vth[(size_t)B_ * H_ * D_ * T_];  // [B,H,D,T]

__device__ __forceinline__ float fast_exp2(float x) {
    float r;
    asm("ex2.approx.ftz.f32 %0, %1;" : "=f"(r) : "f"(x));
    return r;
}

__device__ __forceinline__ uint32_t smem_u32(const void* p) {
    return (uint32_t)__cvta_generic_to_shared(p);
}

__device__ __forceinline__ uint32_t pack_f16(float lo, float hi) {
    uint32_t r;
    asm("cvt.rn.f16x2.f32 %0, %1, %2;" : "=r"(r) : "f"(hi), "f"(lo));
    return r;
}

// ======================= small helper kernels =======================

__global__ void prep_x_kernel(const float* __restrict__ X, float* __restrict__ xsq,
                              __half* __restrict__ Xh)
{
    int m = blockIdx.x;
    int tid = threadIdx.x;
    size_t i = (size_t)m * C_ + tid * 4;
    float4 v = *(const float4*)(X + i);
    *(__half2*)(Xh + i)     = __floats2half2_rn(v.x, v.y);
    *(__half2*)(Xh + i + 2) = __floats2half2_rn(v.z, v.w);

    float s = v.x * v.x + v.y * v.y + v.z * v.z + v.w * v.w;
#pragma unroll
    for (int o = 16; o; o >>= 1) s += __shfl_xor_sync(0xffffffffu, s, o);
    __shared__ float red[8];
    if ((tid & 31) == 0) red[tid >> 5] = s;
    __syncthreads();
    if (tid == 0) {
        float t = 0.f;
#pragma unroll
        for (int j = 0; j < 8; j++) t += red[j];
        xsq[m] = t;
    }
}

__global__ void wconv_kernel(const float* __restrict__ W,
                             __half* __restrict__ WhT,
                             float* __restrict__ wsq,
                             int K, int N)
{
    __shared__ float tile[32][33];
    int bx = blockIdx.x, by = blockIdx.y;
    int tx = threadIdx.x & 31, ty = threadIdx.x >> 5;
#pragma unroll
    for (int i = ty; i < 32; i += 8)
        tile[i][tx] = W[(size_t)(by * 32 + i) * N + bx * 32 + tx];
    __syncthreads();
#pragma unroll
    for (int i = ty; i < 32; i += 8) {
        int n = bx * 32 + i, k = by * 32 + tx;
        float v = tile[tx][i];
        WhT[(size_t)n * K + k] = __float2half_rn(v);
        float s = v * v;
#pragma unroll
        for (int o = 16; o; o >>= 1) s += __shfl_xor_sync(0xffffffffu, s, o);
        if (tx == 0) atomicAdd(wsq + n, s);
    }
}

// ======================= mma.sync helpers =======================

#define LDSM4(r0, r1, r2, r3, addr) \
    asm volatile("ldmatrix.sync.aligned.m8n8.x4.shared.b16 {%0,%1,%2,%3}, [%4];" \
                 : "=r"(r0), "=r"(r1), "=r"(r2), "=r"(r3) : "r"(addr))

#define MMA16816(d, a, b) \
    asm volatile("mma.sync.aligned.m16n8k16.row.col.f32.f16.f16.f32 " \
                 "{%0,%1,%2,%3}, {%4,%5,%6,%7}, {%8,%9}, {%0,%1,%2,%3};" \
                 : "+f"((d)[0]), "+f"((d)[1]), "+f"((d)[2]), "+f"((d)[3]) \
                 : "r"((a)[0]), "r"((a)[1]), "r"((a)[2]), "r"((a)[3]), \
                   "r"((b)[0]), "r"((b)[1]))

__device__ __forceinline__ void cp16(uint32_t dst, const void* src) {
    asm volatile("cp.async.cg.shared.global [%0], [%1], 16;" :: "r"(dst), "l"(src));
}

// ======================= GEMM core (pure fp16, warp 64x32, 8 warps, 3-stage) =======================
#define ROWB   144                 // 128B data + 16B pad, conflict-free ldmatrix
#define TILEB  (128 * ROWB)        // 18432
#define OFF_A  0
#define OFF_B  TILEB
#define STAGEB (2 * TILEB)         // 36864
#define MMA_SMEM (3 * STAGEB)      // 110592

__device__ __forceinline__ void load_stage(
    uint32_t st, const __half* Ag, const __half* Bg,
    int k0, int K, int tid)
{
#pragma unroll
    for (int it = 0; it < 4; it++) {
        int idx = it * 256 + tid;          // 0..1023
        int row = idx >> 3;                // 0..127
        int ch = (idx & 7) * 16;           // 8 x 16B = 128B (64 fp16)
        uint32_t dst = (uint32_t)row * ROWB + ch;
        size_t srcel = (size_t)row * K + k0;
        cp16(st + OFF_A + dst, (const char*)(Ag + srcel) + ch);
        cp16(st + OFF_B + dst, (const char*)(Bg + srcel) + ch);
    }
}

// single-pass mainloop over one BK=64 chunk (4 k-steps)
__device__ __forceinline__ void gemm_chunk(
    uint32_t st, uint32_t aSel, uint32_t bSel, int warpM, int warpN,
    float acc[4][4][4])
{
#pragma unroll
    for (int ks = 0; ks < 4; ks++) {
        const uint32_t aB = st + OFF_A + (uint32_t)warpM * 64 * ROWB + aSel + ks * 32;
        const uint32_t bB = st + OFF_B + (uint32_t)warpN * 32 * ROWB + bSel + ks * 32;
        uint32_t ah4[4][4];
#pragma unroll
        for (int mt = 0; mt < 4; mt++)
            LDSM4(ah4[mt][0], ah4[mt][1], ah4[mt][2], ah4[mt][3],
                  aB + mt * (16 * ROWB));
        uint32_t bh[4][2];
#pragma unroll
        for (int nt2 = 0; nt2 < 2; nt2++) {
            uint32_t r0, r1, r2, r3;
            LDSM4(r0, r1, r2, r3, bB + nt2 * (16 * ROWB));
            bh[nt2 * 2 + 0][0] = r0; bh[nt2 * 2 + 0][1] = r1;
            bh[nt2 * 2 + 1][0] = r2; bh[nt2 * 2 + 1][1] = r3;
        }
#pragma unroll
        for (int mt = 0; mt < 4; mt++)
#pragma unroll
            for (int nt = 0; nt < 4; nt++)
                MMA16816(acc[mt][nt], ah4[mt], bh[nt]);
    }
}

// GEMM mainloop driver: 3-stage pipeline, ONE __syncthreads per chunk
#define GEMM_MAIN(Agh, Bgh, K)                                                 \
    float acc[4][4][4];                                                        \
    _Pragma("unroll")                                                          \
    for (int i = 0; i < 4; i++)                                                \
        _Pragma("unroll")                                                      \
        for (int j = 0; j < 4; j++)                                            \
            _Pragma("unroll")                                                  \
            for (int e = 0; e < 4; e++) acc[i][j][e] = 0.f;                    \
    load_stage(sb, Agh, Bgh, 0, K, tid);                                       \
    asm volatile("cp.async.commit_group;" ::: "memory");                       \
    load_stage(sb + STAGEB, Agh, Bgh, 64, K, tid);                             \
    asm volatile("cp.async.commit_group;" ::: "memory");                       \
    const int NC = (K) >> 6;                                                   \
    int slot = 0;                                                              \
    for (int c = 0; c < NC; c++) {                                             \
        if (c + 1 < NC) {                                                      \
            asm volatile("cp.async.wait_group 1;" ::: "memory");               \
        } else {                                                               \
            asm volatile("cp.async.wait_group 0;" ::: "memory");               \
        }                                                                      \
        __syncthreads();                                                       \
        const uint32_t stb = sb + (uint32_t)slot * STAGEB;                     \
        if (++slot == 3) slot = 0;                                             \
        if (c + 2 < NC) {                                                      \
            int ns = slot + 1; if (ns == 3) ns = 0;                            \
            load_stage(sb + (uint32_t)ns * STAGEB, Agh, Bgh, (c + 2) << 6, K,  \
                       tid);                                                   \
            asm volatile("cp.async.commit_group;" ::: "memory");               \
        }                                                                      \
        gemm_chunk(stb, aSel, bSel, warpM, warpN, acc);                        \
    }

// ======================= GEMM2: yat -> fp32 out =======================
__global__ void __launch_bounds__(256, 2) yat_mma_gemm_kernel(
    const __half* __restrict__ Ah, const __half* __restrict__ BhT,
    const float* __restrict__ asq, const float* __restrict__ bsq,
    const float* __restrict__ bias, float* __restrict__ Cout,
    int M, int N, int K, float scale)
{
    extern __shared__ char smem[];
    const uint32_t sb = smem_u32(smem);

    const int tid = threadIdx.x;
    const int wid = tid >> 5, lane = tid & 31;
    const int warpM = wid >> 2;
    const int warpN = wid & 3;
    const int rowBase = blockIdx.y * 128;
    const int colBase = blockIdx.x * 128;

    const __half* Agh = Ah + (size_t)rowBase * K;
    const __half* Bgh = BhT + (size_t)colBase * K;

    const uint32_t aSel = (uint32_t)(lane & 15) * ROWB + (uint32_t)(lane >> 4) * 16;
    const uint32_t bSel = (uint32_t)(((lane >> 4) & 1) * 8 + (lane & 7)) * ROWB +
                          (uint32_t)((lane >> 3) & 1) * 16;

    GEMM_MAIN(Agh, Bgh, K)

    const int lr = lane >> 2, lc = (lane & 3) * 2;
    const int mW = rowBase + warpM * 64;
    const int nW = colBase + warpN * 32;
#pragma unroll
    for (int mt = 0; mt < 4; mt++) {
        const int r0g = mW + mt * 16 + lr;
        const int r1g = r0g + 8;
        const float av0 = asq[r0g];
        const float av1 = asq[r1g];
#pragma unroll
        for (int nt = 0; nt < 4; nt++) {
            const int cg = nW + nt * 8 + lc;
            const float bq0 = bsq[cg], bq1 = bsq[cg + 1];
            const float bi0 = bias[cg], bi1 = bias[cg + 1];
            float d00 = acc[mt][nt][0], d01 = acc[mt][nt][1];
            float d10 = acc[mt][nt][2], d11 = acc[mt][nt][3];
            float2 o0, o1;
            o0.x = __fdividef(d00 * d00, av0 + bq0 - 2.f * d00 + EPS_) * scale + bi0;
            o0.y = __fdividef(d01 * d01, av0 + bq1 - 2.f * d01 + EPS_) * scale + bi1;
            o1.x = __fdividef(d10 * d10, av1 + bq0 - 2.f * d10 + EPS_) * scale + bi0;
            o1.y = __fdividef(d11 * d11, av1 + bq1 - 2.f * d11 + EPS_) * scale + bi1;
            *(float2*)(Cout + (size_t)r0g * N + cg) = o0;
            *(float2*)(Cout + (size_t)r1g * N + cg) = o1;
        }
    }
}

// ======================= GEMM1: yat + RoPE + fp16 fused epilogue =======================
__global__ void __launch_bounds__(256, 2) yat_rope_gemm_kernel(
    const __half* __restrict__ Ah, const __half* __restrict__ BhT,
    const float* __restrict__ asq, const float* __restrict__ bsq,
    const float* __restrict__ bias,
    __half* __restrict__ Qh, __half* __restrict__ Kh,
    __half* __restrict__ VTh,
    float scale)
{
    extern __shared__ char smem[];
    const uint32_t sb = smem_u32(smem);
    const int K = C_;

    const int tid = threadIdx.x;
    const int wid = tid >> 5, lane = tid & 31;
    const int warpM = wid >> 2;
    const int warpN = wid & 3;
    const int rowBase = blockIdx.y * 128;
    const int colBase = blockIdx.x * 128;

    const __half* Agh = Ah + (size_t)rowBase * K;
    const __half* Bgh = BhT + (size_t)colBase * K;

    const uint32_t aSel = (uint32_t)(lane & 15) * ROWB + (uint32_t)(lane >> 4) * 16;
    const uint32_t bSel = (uint32_t)(((lane >> 4) & 1) * 8 + (lane & 7)) * ROWB +
                          (uint32_t)((lane >> 3) & 1) * 16;

    GEMM_MAIN(Agh, Bgh, K)

    // ---- epilogue: yat + bias, then RoPE/split per segment ----
    const int lr = lane >> 2, lc = (lane & 3) * 2;
    const int mW = rowBase + warpM * 64;
    const int nW = colBase + warpN * 32;
    const int seg = colBase >> 10;                 // 0=Q, 1=K, 2=V
    const float QSC = 0.125f * 1.4426950408889634f;

    float fr[4];
#pragma unroll
    for (int nt = 0; nt < 4; nt++) {
        int cg = nW + nt * 8 + lc;
        int i = (cg & 63) >> 1;
        fr[nt] = powf(10000.0f, -(float)i / 32.0f);
    }

#pragma unroll
    for (int mt = 0; mt < 4; mt++) {
        const int r0g = mW + mt * 16 + lr;
        const int r1g = r0g + 8;
        const float av0 = asq[r0g];
        const float av1 = asq[r1g];
        const int b0 = r0g >> 11, t0 = r0g & 2047;
        const int b1 = r1g >> 11, t1 = r1g & 2047;
#pragma unroll
        for (int nt = 0; nt < 4; nt++) {
            const int cg = nW + nt * 8 + lc;
            const float bq0 = bsq[cg], bq1 = bsq[cg + 1];
            const float bi0 = bias[cg], bi1 = bias[cg + 1];
            float d00 = acc[mt][nt][0], d01 = acc[mt][nt][1];
            float d10 = acc[mt][nt][2], d11 = acc[mt][nt][3];
            float y00 = __fdividef(d00 * d00, av0 + bq0 - 2.f * d00 + EPS_) * scale + bi0;
            float y01 = __fdividef(d01 * d01, av0 + bq1 - 2.f * d01 + EPS_) * scale + bi1;
            float y10 = __fdividef(d10 * d10, av1 + bq0 - 2.f * d10 + EPS_) * scale + bi0;
            float y11 = __fdividef(d11 * d11, av1 + bq1 - 2.f * d11 + EPS_) * scale + bi1;

            const int colh = cg & 1023;
            const int h = colh >> 6;
            const int d = colh & 63;

            if (seg < 2) {
                float s0, c0, s1, c1;
                sincosf((float)t0 * fr[nt], &s0, &c0);
                sincosf((float)t1 * fr[nt], &s1, &c1);
                float sc = (seg == 0) ? QSC : 1.0f;
                float a0 = (y00 * c0 - y01 * s0) * sc;
                float a1 = (y01 * c0 + y00 * s0) * sc;
                float e0 = (y10 * c1 - y11 * s1) * sc;
                float e1 = (y11 * c1 + y10 * s1) * sc;
                __half* Dst = (seg == 0) ? Qh : Kh;
                size_t o0 = ((size_t)(b0 * H_ + h) * T_ + t0) * D_ + d;
                size_t o1 = ((size_t)(b1 * H_ + h) * T_ + t1) * D_ + d;
                *(__half2*)(Dst + o0) = __floats2half2_rn(a0, a1);
                *(__half2*)(Dst + o1) = __floats2half2_rn(e0, e1);
            } else {
                size_t ov0 = ((size_t)(b0 * H_ + h) * D_ + d) * T_ + t0;
                size_t ov1 = ((size_t)(b1 * H_ + h) * D_ + d) * T_ + t1;
                VTh[ov0]      = __float2half_rn(y00);
                VTh[ov0 + T_] = __float2half_rn(y01);
                VTh[ov1]      = __float2half_rn(y10);
                VTh[ov1 + T_] = __float2half_rn(y11);
            }
        }
    }
}

// ======================= tensor-core causal flash attention (pure fp16, 3-stage) =======================
#define AROWB 144
#define QTILE (128 * AROWB)
#define KVTILE (64 * AROWB)
#define SQH_OFF 0
#define STG_OFF QTILE
#define STGSZ  (2 * KVTILE)          // KH + VH = 18432
#define ST_KH 0
#define ST_VH (1 * KVTILE)
#define ATTN_SMEM (QTILE + 3 * STGSZ)   // 73728

__device__ __forceinline__ void attn_load_stage(
    uint32_t st, const __half* kh, const __half* vth,
    size_t bhT, size_t bhD, int k0, int tid)
{
#pragma unroll
    for (int it = 0; it < 2; it++) {
        int idx = it * 256 + tid;
        int row = idx >> 3;
        int ch = (idx & 7) * 16;
        uint32_t dst = (uint32_t)row * AROWB + ch;
        cp16(st + ST_KH + dst, (const char*)(kh + (bhT + k0 + row) * D_) + ch);
        cp16(st + ST_VH + dst, (const char*)(vth + (bhD + row) * T_ + k0) + ch);
    }
}

__global__ void __launch_bounds__(256, 2) attn_mma_kernel(
    const __half* __restrict__ qh, const __half* __restrict__ kh,
    const __half* __restrict__ vth,
    __half* __restrict__ Oh, float* __restrict__ osq)
{
    extern __shared__ char smem[];
    const uint32_t sb = smem_u32(smem);

    const int bh = blockIdx.y;
    const int qx = 15 - (int)blockIdx.x;
    const int q0 = qx * 128;
    const size_t bhT = (size_t)bh * T_;
    const size_t bhD = (size_t)bh * D_;

    const int tid = threadIdx.x;
    const int wid = tid >> 5, lane = tid & 31;
    const int lr = lane >> 2, c2 = (lane & 3) * 2;

    const uint32_t aSel = (uint32_t)(lane & 15) * AROWB + (uint32_t)(lane >> 4) * 16;
    const uint32_t bSel = (uint32_t)(((lane >> 4) & 1) * 8 + (lane & 7)) * AROWB +
                          (uint32_t)((lane >> 3) & 1) * 16;

    const int ntiles = 2 * qx + 2;

#pragma unroll
    for (int it = 0; it < 4; it++) {
        int idx = it * 256 + tid;
        int row = idx >> 3;
        int ch = (idx & 7) * 16;
        uint32_t dst = (uint32_t)row * AROWB + ch;
        cp16(sb + SQH_OFF + dst, (const char*)(qh + (bhT + q0 + row) * D_) + ch);
    }
    attn_load_stage(sb + STG_OFF, kh, vth, bhT, bhD, 0, tid);
    asm volatile("cp.async.commit_group;" ::: "memory");
    attn_load_stage(sb + STG_OFF + STGSZ, kh, vth, bhT, bhD, 64, tid);
    asm volatile("cp.async.commit_group;" ::: "memory");

    asm volatile("cp.async.wait_group 1;" ::: "memory");
    __syncthreads();
    uint32_t qhf[4][4];
    {
        const uint32_t aQ = sb + SQH_OFF + (uint32_t)wid * 16 * AROWB + aSel;
#pragma unroll
        for (int ks = 0; ks < 4; ks++)
            LDSM4(qhf[ks][0], qhf[ks][1], qhf[ks][2], qhf[ks][3], aQ + ks * 32);
    }

    float O[8][4];
#pragma unroll
    for (int j = 0; j < 8; j++)
#pragma unroll
        for (int e = 0; e < 4; e++) O[j][e] = 0.f;
    float mrow[2] = {-1e30f, -1e30f};
    float lrow[2] = {0.f, 0.f};

    const int rowg0 = q0 + wid * 16 + lr;
    int slot = 0;

    for (int kt = 0; kt < ntiles; kt++) {
        if (kt + 1 < ntiles) {
            asm volatile("cp.async.wait_group 1;" ::: "memory");
        } else {
            asm volatile("cp.async.wait_group 0;" ::: "memory");
        }
        __syncthreads();
        const uint32_t st = sb + STG_OFF + (uint32_t)slot * STGSZ;
        if (++slot == 3) slot = 0;
        if (kt + 2 < ntiles) {
            int ns = slot + 1; if (ns == 3) ns = 0;
            attn_load_stage(sb + STG_OFF + (uint32_t)ns * STGSZ,
                            kh, vth, bhT, bhD, (kt + 2) * 64, tid);
            asm volatile("cp.async.commit_group;" ::: "memory");
        }

        float S[8][4];
#pragma unroll
        for (int j = 0; j < 8; j++)
#pragma unroll
            for (int e = 0; e < 4; e++) S[j][e] = 0.f;

#pragma unroll
        for (int ks = 0; ks < 4; ks++) {
#pragma unroll
            for (int np = 0; np < 4; np++) {
                uint32_t r0, r1, r2, r3;
                LDSM4(r0, r1, r2, r3, st + ST_KH + np * (16 * AROWB) + bSel + ks * 32);
                uint32_t bh0[2] = {r0, r1}, bh1[2] = {r2, r3};
                MMA16816(S[np * 2 + 0], qhf[ks], bh0);
                MMA16816(S[np * 2 + 1], qhf[ks], bh1);
            }
        }

        const int k0 = kt * 64;
        if (kt >= 2 * qx) {
#pragma unroll
            for (int j = 0; j < 8; j++) {
                int col = k0 + j * 8 + c2;
                if (col > rowg0)     S[j][0] = -1e30f;
                if (col + 1 > rowg0) S[j][1] = -1e30f;
                if (col > rowg0 + 8)     S[j][2] = -1e30f;
                if (col + 1 > rowg0 + 8) S[j][3] = -1e30f;
            }
        }

#pragma unroll
        for (int i = 0; i < 2; i++) {
            float mx = -1e30f;
#pragma unroll
            for (int j = 0; j < 8; j++)
                mx = fmaxf(mx, fmaxf(S[j][2 * i], S[j][2 * i + 1]));
            mx = fmaxf(mx, __shfl_xor_sync(0xffffffffu, mx, 1));
            mx = fmaxf(mx, __shfl_xor_sync(0xffffffffu, mx, 2));
            float mn = fmaxf(mrow[i], mx);
            float cf = fast_exp2(mrow[i] - mn);
            mrow[i] = mn;
            float rs = 0.f;
#pragma unroll
            for (int j = 0; j < 8; j++) {
                float p0 = fast_exp2(S[j][2 * i] - mn);
                float p1 = fast_exp2(S[j][2 * i + 1] - mn);
                S[j][2 * i] = p0; S[j][2 * i + 1] = p1;
                rs += p0 + p1;
            }
            rs += __shfl_xor_sync(0xffffffffu, rs, 1);
            rs += __shfl_xor_sync(0xffffffffu, rs, 2);
            lrow[i] = lrow[i] * cf + rs;
#pragma unroll
            for (int j = 0; j < 8; j++) { O[j][2 * i] *= cf; O[j][2 * i + 1] *= cf; }
        }

        uint32_t PH[4][4];
#pragma unroll
        for (int t = 0; t < 4; t++) {
#pragma unroll
            for (int h2 = 0; h2 < 2; h2++) {
                int j = 2 * t + h2;
                PH[t][h2 * 2 + 0] = pack_f16(S[j][0], S[j][1]);
                PH[t][h2 * 2 + 1] = pack_f16(S[j][2], S[j][3]);
            }
        }

#pragma unroll
        for (int t = 0; t < 4; t++) {
#pragma unroll
            for (int dn = 0; dn < 4; dn++) {
                uint32_t r0, r1, r2, r3;
                LDSM4(r0, r1, r2, r3, st + ST_VH + dn * (16 * AROWB) + bSel + t * 32);
                uint32_t vh0[2] = {r0, r1}, vh1[2] = {r2, r3};
                MMA16816(O[dn * 2 + 0], PH[t], vh0);
                MMA16816(O[dn * 2 + 1], PH[t], vh1);
            }
        }
    }

    const int b = bh >> 4, h = bh & 15;
    const float inv0 = 1.f / lrow[0], inv1 = 1.f / lrow[1];
    const size_t m0 = (size_t)(b * T_ + rowg0);
    const size_t m1 = m0 + 8;
    __half* oh0 = Oh + m0 * C_ + h * 64;
    __half* oh1 = Oh + m1 * C_ + h * 64;
    float sq0 = 0.f, sq1 = 0.f;
#pragma unroll
    for (int j = 0; j < 8; j++) {
        float y0 = O[j][0] * inv0, y1 = O[j][1] * inv0;
        float y2 = O[j][2] * inv1, y3 = O[j][3] * inv1;
        sq0 += y0 * y0 + y1 * y1;
        sq1 += y2 * y2 + y3 * y3;
        *(__half2*)(oh0 + j * 8 + c2) = __floats2half2_rn(y0, y1);
        *(__half2*)(oh1 + j * 8 + c2) = __floats2half2_rn(y2, y3);
    }
    sq0 += __shfl_xor_sync(0xffffffffu, sq0, 1);
    sq0 += __shfl_xor_sync(0xffffffffu, sq0, 2);
    sq1 += __shfl_xor_sync(0xffffffffu, sq1, 1);
    sq1 += __shfl_xor_sync(0xffffffffu, sq1, 2);
    if ((lane & 3) == 0) {
        atomicAdd(osq + m0, sq0);
        atomicAdd(osq + m1, sq1);
    }
}

// ---------------- launcher (serial single-stream; best measured config) ----------------
extern "C" void kernel_launch(void* const* d_in, const int* in_sizes, int n_in,
                              void* d_out, int out_size)
{
    (void)in_sizes; (void)n_in; (void)out_size;
    const float* x      = (const float*)d_in[0];
    const float* w_attn = (const float*)d_in[2];
    const float* b_attn = (const float*)d_in[3];
    const float* w_proj = (const float*)d_in[4];
    const float* b_proj = (const float*)d_in[5];
    float* out = (float*)d_out;

    float *xsq, *osq, *wsq1, *wsq2;
    __half *xh, *ah, *w1h, *w2h;
    __half *qbh, *kbh, *vth;
    cudaGetSymbolAddress((void**)&xsq,  g_xsq);
    cudaGetSymbolAddress((void**)&osq,  g_osq);
    cudaGetSymbolAddress((void**)&wsq1, g_wsq1);
    cudaGetSymbolAddress((void**)&wsq2, g_wsq2);
    cudaGetSymbolAddress((void**)&xh,   g_xh);
    cudaGetSymbolAddress((void**)&ah,   g_ah);
    cudaGetSymbolAddress((void**)&w1h,  g_w1h);
    cudaGetSymbolAddress((void**)&w2h,  g_w2h);
    cudaGetSymbolAddress((void**)&qbh,  g_qbh);
    cudaGetSymbolAddress((void**)&kbh,  g_kbh);
    cudaGetSymbolAddress((void**)&vth,  g_vth);

    const float scale1 = (float)(sqrt(3072.0) / log1p(3072.0));
    const float scale2 = (float)(sqrt(1024.0) / log1p(1024.0));

    cudaFuncSetAttribute(yat_mma_gemm_kernel,
                         cudaFuncAttributeMaxDynamicSharedMemorySize, MMA_SMEM);
    cudaFuncSetAttribute(yat_rope_gemm_kernel,
                         cudaFuncAttributeMaxDynamicSharedMemorySize, MMA_SMEM);
    cudaFuncSetAttribute(attn_mma_kernel,
                         cudaFuncAttributeMaxDynamicSharedMemorySize, ATTN_SMEM);

    cudaMemsetAsync(wsq1, 0, N1_ * sizeof(float));
    cudaMemsetAsync(wsq2, 0, C_ * sizeof(float));
    cudaMemsetAsync(osq,  0, M_ * sizeof(float));

    prep_x_kernel<<<M_, 256>>>(x, xsq, xh);
    wconv_kernel<<<dim3(N1_ / 32, C_ / 32), 256>>>(w_attn, w1h, wsq1, C_, N1_);
    wconv_kernel<<<dim3(C_ / 32, C_ / 32), 256>>>(w_proj, w2h, wsq2, C_, C_);

    yat_rope_gemm_kernel<<<dim3(N1_ / 128, M_ / 128), 256, MMA_SMEM>>>(
        xh, w1h, xsq, wsq1, b_attn, qbh, kbh, vth, scale1);

    attn_mma_kernel<<<dim3(T_ / 128, B_ * H_), 256, ATTN_SMEM>>>(
        qbh, kbh, vth, ah, osq);

    yat_mma_gemm_kernel<<<dim3(C_ / 128, M_ / 128), 256, MMA_SMEM>>>(
        ah, w2h, osq, wsq2, b_proj, out, M_, C_, C_, scale2);
}